// round 12
// baseline (speedup 1.0000x reference)
#include <cuda_runtime.h>

// LSTM B=4096, T=999, I=1, H=51, O=1, future=0.
//
// R10 core (gate-pair threads: p0=(i,g), p1=(f,o)+cell; 104 weight regs;
// tanh.approx; one barrier/step; batch-major h; deferred FC lanes),
// rescheduled for W=4 warps/SMSP:
//   BT=7, grid=586 <= 592 (4 CTAs/SM) -> still ONE wave, and the per-SMSP
//   residual (~4300/W) drops 2075 -> ~1500 cyc/step. FMA floor also dips
//   (586*7=4102 ~ 4096: no BT padding waste).
// Register economy for the 128-reg cap: chunks of 2 batches (8 accum regs),
// cst = 3 u64 + 1 float, clobbers between chunks to stop LDS hoisting.
// xsh rows padded to 8 floats so float2 x reads stay 8B-aligned.

#define HID    51
#define KP     26
#define SEQLEN 999
#define BT     7
#define XPAD   8
#define NTHR   128
#define BATCH  4096
#define GRID   586          // ceil(4096/7)

typedef unsigned long long u64;
template <int N> struct IC { static constexpr int v = N; };

__device__ __forceinline__ u64 pk2(float lo, float hi) {
    u64 r;
    asm("mov.b64 %0, {%1, %2};"
        : "=l"(r) : "r"(__float_as_uint(lo)), "r"(__float_as_uint(hi)));
    return r;
}
__device__ __forceinline__ void upk2(u64 v, float& lo, float& hi) {
    unsigned a, b;
    asm("mov.b64 {%0, %1}, %2;" : "=r"(a), "=r"(b) : "l"(v));
    lo = __uint_as_float(a); hi = __uint_as_float(b);
}
__device__ __forceinline__ u64 ffma2(u64 a, u64 b, u64 c) {
    u64 d; asm("fma.rn.f32x2 %0, %1, %2, %3;" : "=l"(d) : "l"(a), "l"(b), "l"(c));
    return d;
}
__device__ __forceinline__ u64 fmul2(u64 a, u64 b) {
    u64 d; asm("mul.rn.f32x2 %0, %1, %2;" : "=l"(d) : "l"(a), "l"(b));
    return d;
}
__device__ __forceinline__ float tanha(float x) {
    float r; asm("tanh.approx.f32 %0, %1;" : "=f"(r) : "f"(x));
    return r;
}

__global__ __launch_bounds__(NTHR, 4)
void lstm11_kernel(const float* __restrict__ input,   // (B, T, 1)
                   const float* __restrict__ W_ih,    // (4H, 1)
                   const float* __restrict__ W_hh,    // (4H, H)
                   const float* __restrict__ b_ih,    // (4H)
                   const float* __restrict__ b_hh,    // (4H)
                   const float* __restrict__ W_fc,    // (1, H)
                   const float* __restrict__ b_fc,    // (1)
                   float* __restrict__ out)           // (B, T, 1)
{
    __shared__ __align__(16) float xsh[SEQLEN][XPAD];  // 31.97 KB (padded)
    __shared__ __align__(16) u64   hsh[2][BT][KP];     // 2.91 KB, batch-major
    __shared__ __align__(16) u64   wfc2[KP];

    const int tid = threadIdx.x;
    const int b0  = blockIdx.x * BT;

    // ---- one-time init (batch-clamped for the last CTA) ----
    #pragma unroll
    for (int b = 0; b < BT; b++) {
        const int bidx = min(b0 + b, BATCH - 1);
        for (int idx = tid; idx < SEQLEN; idx += NTHR)
            xsh[idx][b] = input[bidx * SEQLEN + idx];
    }
    for (int idx = tid; idx < 2 * BT * KP; idx += NTHR)
        ((u64*)hsh)[idx] = 0ull;                      // h0 = 0 (+ pad lanes)
    if (tid < KP)
        wfc2[tid] = pk2(W_fc[2 * tid],
                        (2 * tid + 1 < HID) ? W_fc[2 * tid + 1] : 0.0f);

    const int j = tid >> 1;           // unit 0..50 (active)
    const int p = tid & 1;            // 0 = (i,g), 1 = (f,o)+cell
    const bool active = (tid < 2 * HID);              // < 102
    const bool fcRole = (tid >= 104 && tid < 104 + BT);
    const int  fb     = tid - 104;
    const unsigned wmask = (tid >= 96) ? 0x3Fu : 0xFFFFFFFFu;

    const int row1 = p * HID + j;         // i or f
    const int row2 = (2 + p) * HID + j;   // g or o

    u64 w1[KP], w2[KP];
    float bias1 = 0.f, bias2 = 0.f, wih1 = 0.f, wih2 = 0.f;
    if (active) {
        #pragma unroll
        for (int q = 0; q < KP; q++) {
            int k0 = 2 * q, k1 = 2 * q + 1;
            float a0 = W_hh[row1 * HID + k0];
            float a1 = (k1 < HID) ? W_hh[row1 * HID + k1] : 0.0f;
            float c0 = W_hh[row2 * HID + k0];
            float c1 = (k1 < HID) ? W_hh[row2 * HID + k1] : 0.0f;
            w1[q] = pk2(a0, a1);
            w2[q] = pk2(c0, c1);
        }
        bias1 = b_ih[row1] + b_hh[row1];
        bias2 = b_ih[row2] + b_hh[row2];
        wih1  = W_ih[row1];
        wih2  = W_ih[row2];
    } else {
        #pragma unroll
        for (int q = 0; q < KP; q++) { w1[q] = 0ull; w2[q] = 0ull; }
    }
    const float bfc = b_fc[0];

    // act = m2 * tanh(sc2 * a) + a2c  (row1 always sigmoid; row2: g->tanh,
    // o->sigmoid).  sigmoid(x) = 0.5*tanh(0.5x) + 0.5.
    const float sc2 = (p == 0) ? 1.0f : 0.5f;
    const float m2  = (p == 0) ? 1.0f : 0.5f;
    const float a2c = (p == 0) ? 0.0f : 0.5f;

    u64   cst0 = 0ull, cst1 = 0ull, cst2 = 0ull;   // batch pairs 01,23,45
    float cstS = 0.0f;                             // batch 6

    __syncthreads();

    #pragma unroll 1
    for (int t = 0; t < SEQLEN; t++) {
        const u64* __restrict__ hb = &hsh[t & 1][0][0];
        u64* __restrict__ hw = &hsh[(t + 1) & 1][0][0];
        const float* __restrict__ xrow = &xsh[t][0];

        // ---- deferred FC for step t-1 (idle lanes; stable buffer) ----
        if (fcRole && t > 0) {
            const u64* __restrict__ hv = hb + fb * KP;
            u64 s0 = 0ull, s1 = 0ull;
            #pragma unroll
            for (int q = 0; q < KP; q += 2) {
                s0 = ffma2(hv[q],     wfc2[q],     s0);
                s1 = ffma2(hv[q + 1], wfc2[q + 1], s1);
            }
            float aa, ab, ac, ad;
            upk2(s0, aa, ab); upk2(s1, ac, ad);
            if (b0 + fb < BATCH)
                out[(b0 + fb) * SEQLEN + (t - 1)] = (aa + ab) + (ac + ad) + bfc;
        }

        if (active) {
            // 2-batch chunk: compile-time indices only.
            auto chunkf = [&](int cb, u64& cc) {
                u64 A0 = 0ull, A1 = 0ull, C0 = 0ull, C1 = 0ull;
                #pragma unroll
                for (int q = 0; q < KP; q += 2) {
                    ulonglong2 u0 = *(const ulonglong2*)(hb + cb * KP + q);
                    ulonglong2 u1 = *(const ulonglong2*)(hb + (cb + 1) * KP + q);
                    A0 = ffma2(w1[q], u0.x, A0); A0 = ffma2(w1[q + 1], u0.y, A0);
                    A1 = ffma2(w1[q], u1.x, A1); A1 = ffma2(w1[q + 1], u1.y, A1);
                    C0 = ffma2(w2[q], u0.x, C0); C0 = ffma2(w2[q + 1], u0.y, C0);
                    C1 = ffma2(w2[q], u1.x, C1); C1 = ffma2(w2[q + 1], u1.y, C1);
                }
                const float2 xv = *(const float2*)(xrow + cb);
                float lo, hi;
                upk2(A0, lo, hi); const float g10 = (lo + hi) + fmaf(xv.x, wih1, bias1);
                upk2(A1, lo, hi); const float g11 = (lo + hi) + fmaf(xv.y, wih1, bias1);
                upk2(C0, lo, hi); const float g20 = (lo + hi) + fmaf(xv.x, wih2, bias2);
                upk2(C1, lo, hi); const float g21 = (lo + hi) + fmaf(xv.y, wih2, bias2);

                const float s10 = fmaf(0.5f, tanha(0.5f * g10), 0.5f);
                const float s11 = fmaf(0.5f, tanha(0.5f * g11), 0.5f);
                const float s20 = fmaf(m2, tanha(sc2 * g20), a2c);
                const float s21 = fmaf(m2, tanha(sc2 * g21), a2c);

                u64 a1p = pk2(s10, s11);
                u64 a2p = pk2(s20, s21);
                u64 pr  = fmul2(a1p, a2p);             // p0: sig(i)*tanh(g)
                u64 rr  = __shfl_xor_sync(wmask, pr, 1, 32);
                if (p == 1) {
                    cc = ffma2(a1p, cc, rr);           // c = sig(f)*c + ...
                    float c0f, c1f; upk2(cc, c0f, c1f);
                    const float h0v = s20 * tanha(c0f);
                    const float h1v = s21 * tanha(c1f);
                    const int jh = j >> 1, jl = j & 1;
                    ((float*)(hw + cb * KP + jh))[jl]       = h0v;
                    ((float*)(hw + (cb + 1) * KP + jh))[jl] = h1v;
                }
            };

            chunkf(0, cst0);
            asm volatile("" ::: "memory");
            chunkf(2, cst1);
            asm volatile("" ::: "memory");
            chunkf(4, cst2);
            asm volatile("" ::: "memory");

            // ---- tail: single batch 6 (scalar path) ----
            {
                u64 A = 0ull, C = 0ull;
                #pragma unroll
                for (int q = 0; q < KP; q += 2) {
                    ulonglong2 u = *(const ulonglong2*)(hb + 6 * KP + q);
                    A = ffma2(w1[q], u.x, A); A = ffma2(w1[q + 1], u.y, A);
                    C = ffma2(w2[q], u.x, C); C = ffma2(w2[q + 1], u.y, C);
                }
                const float xv = xrow[6];
                float lo, hi;
                upk2(A, lo, hi); const float g1 = (lo + hi) + fmaf(xv, wih1, bias1);
                upk2(C, lo, hi); const float g2 = (lo + hi) + fmaf(xv, wih2, bias2);
                const float s1 = fmaf(0.5f, tanha(0.5f * g1), 0.5f);
                const float s2 = fmaf(m2, tanha(sc2 * g2), a2c);
                const float pr = s1 * s2;              // p0: sig(i)*tanh(g)
                const float rr = __shfl_xor_sync(wmask, pr, 1, 32);
                if (p == 1) {
                    cstS = fmaf(s1, cstS, rr);
                    const float hv6 = s2 * tanha(cstS);
                    const int jh = j >> 1, jl = j & 1;
                    ((float*)(hw + 6 * KP + jh))[jl] = hv6;
                }
            }
        }
        __syncthreads();
    }

    // final FC for t = SEQLEN-1
    if (fcRole && b0 + fb < BATCH) {
        const u64* __restrict__ hv = &hsh[SEQLEN & 1][fb][0];
        u64 s0 = 0ull, s1 = 0ull;
        #pragma unroll
        for (int q = 0; q < KP; q += 2) {
            s0 = ffma2(hv[q],     wfc2[q],     s0);
            s1 = ffma2(hv[q + 1], wfc2[q + 1], s1);
        }
        float aa, ab, ac, ad;
        upk2(s0, aa, ab); upk2(s1, ac, ad);
        out[(b0 + fb) * SEQLEN + (SEQLEN - 1)] = (aa + ab) + (ac + ad) + bfc;
    }
}

extern "C" void kernel_launch(void* const* d_in, const int* in_sizes, int n_in,
                              void* d_out, int out_size) {
    const float* input = (const float*)d_in[0];
    const float* W_ih  = (const float*)d_in[1];
    const float* W_hh  = (const float*)d_in[2];
    const float* b_ih  = (const float*)d_in[3];
    const float* b_hh  = (const float*)d_in[4];
    const float* W_fc  = (const float*)d_in[5];
    const float* b_fc  = (const float*)d_in[6];
    // d_in[7] = future (0) — ignored.
    float* out = (float*)d_out;

    lstm11_kernel<<<GRID, NTHR>>>(input, W_ih, W_hh, b_ih, b_hh,
                                  W_fc, b_fc, out);
}

// round 13
// speedup vs baseline: 1.3571x; 1.3571x over previous
#include <cuda_runtime.h>

// LSTM B=4096, T=999, I=1, H=51, O=1, future=0.
//
// R10 config (BT=10, grid=410, 128 thr, 3 CTAs/SM, single wave; gate-pair
// threads p0=(i,g) / p1=(f,o)+cell; 104 weight regs; tanh.approx; one
// barrier/step; batch-major h; deferred FC lanes) with SOFTWARE-PIPELINED
// chunks: step = { dots(0); | dots(1); tail(0); | dots(2); tail(1); |
// tail(2) } with clobbers only between stages. Chunk k's MUFU/shfl/store
// tail now hides under chunk k+1's LDS/FFMA2 instead of extending the
// serial critical path (R10's clobbers fully serialized chunks).
// Peak live accums = 2 chunks = 32 regs -> stays under the 170-reg cap.

#define HID    51
#define KP     26
#define SEQLEN 999
#define BT     10
#define NTHR   128
#define BATCH  4096
#define GRID   410          // ceil(4096/10)

typedef unsigned long long u64;

__device__ __forceinline__ u64 pk2(float lo, float hi) {
    u64 r;
    asm("mov.b64 %0, {%1, %2};"
        : "=l"(r) : "r"(__float_as_uint(lo)), "r"(__float_as_uint(hi)));
    return r;
}
__device__ __forceinline__ void upk2(u64 v, float& lo, float& hi) {
    unsigned a, b;
    asm("mov.b64 {%0, %1}, %2;" : "=r"(a), "=r"(b) : "l"(v));
    lo = __uint_as_float(a); hi = __uint_as_float(b);
}
__device__ __forceinline__ u64 ffma2(u64 a, u64 b, u64 c) {
    u64 d; asm("fma.rn.f32x2 %0, %1, %2, %3;" : "=l"(d) : "l"(a), "l"(b), "l"(c));
    return d;
}
__device__ __forceinline__ u64 fmul2(u64 a, u64 b) {
    u64 d; asm("mul.rn.f32x2 %0, %1, %2;" : "=l"(d) : "l"(a), "l"(b));
    return d;
}
__device__ __forceinline__ float tanha(float x) {
    float r; asm("tanh.approx.f32 %0, %1;" : "=f"(r) : "f"(x));
    return r;
}

__global__ __launch_bounds__(NTHR, 3)
void lstm12_kernel(const float* __restrict__ input,   // (B, T, 1)
                   const float* __restrict__ W_ih,    // (4H, 1)
                   const float* __restrict__ W_hh,    // (4H, H)
                   const float* __restrict__ b_ih,    // (4H)
                   const float* __restrict__ b_hh,    // (4H)
                   const float* __restrict__ W_fc,    // (1, H)
                   const float* __restrict__ b_fc,    // (1)
                   float* __restrict__ out)           // (B, T, 1)
{
    __shared__ __align__(16) float xsh[SEQLEN][BT];   // 39.96 KB
    __shared__ __align__(16) u64   hsh[2][BT][KP];    // 4.16 KB, batch-major
    __shared__ __align__(16) u64   wfc2[KP];

    const int tid = threadIdx.x;
    const int b0  = blockIdx.x * BT;

    // ---- one-time init (batch-clamped for the last CTA) ----
    #pragma unroll
    for (int b = 0; b < BT; b++) {
        const int bidx = min(b0 + b, BATCH - 1);
        for (int idx = tid; idx < SEQLEN; idx += NTHR)
            xsh[idx][b] = input[bidx * SEQLEN + idx];
    }
    for (int idx = tid; idx < 2 * BT * KP; idx += NTHR)
        ((u64*)hsh)[idx] = 0ull;                      // h0 = 0 (+ pad lanes)
    if (tid < KP)
        wfc2[tid] = pk2(W_fc[2 * tid],
                        (2 * tid + 1 < HID) ? W_fc[2 * tid + 1] : 0.0f);

    const int j = tid >> 1;           // unit 0..50 (active)
    const int p = tid & 1;            // 0 = (i,g), 1 = (f,o)+cell
    const bool active = (tid < 2 * HID);              // < 102
    const bool fcRole = (tid >= 104 && tid < 104 + BT);
    const int  fb     = tid - 104;
    const unsigned wmask = (tid >= 96) ? 0x3Fu : 0xFFFFFFFFu;

    const int row1 = p * HID + j;         // i or f
    const int row2 = (2 + p) * HID + j;   // g or o

    u64 w1[KP], w2[KP];
    float bias1 = 0.f, bias2 = 0.f, wih1 = 0.f, wih2 = 0.f;
    if (active) {
        #pragma unroll
        for (int q = 0; q < KP; q++) {
            int k0 = 2 * q, k1 = 2 * q + 1;
            float a0 = W_hh[row1 * HID + k0];
            float a1 = (k1 < HID) ? W_hh[row1 * HID + k1] : 0.0f;
            float c0 = W_hh[row2 * HID + k0];
            float c1 = (k1 < HID) ? W_hh[row2 * HID + k1] : 0.0f;
            w1[q] = pk2(a0, a1);
            w2[q] = pk2(c0, c1);
        }
        bias1 = b_ih[row1] + b_hh[row1];
        bias2 = b_ih[row2] + b_hh[row2];
        wih1  = W_ih[row1];
        wih2  = W_ih[row2];
    } else {
        #pragma unroll
        for (int q = 0; q < KP; q++) { w1[q] = 0ull; w2[q] = 0ull; }
    }
    const float bfc = b_fc[0];

    // act = m2 * tanh(sc2 * a) + a2c  (row1 always sigmoid; row2: g->tanh,
    // o->sigmoid).  sigmoid(x) = 0.5*tanh(0.5x) + 0.5.
    const float sc2 = (p == 0) ? 1.0f : 0.5f;
    const float m2  = (p == 0) ? 1.0f : 0.5f;
    const float a2c = (p == 0) ? 0.0f : 0.5f;

    u64 cst0 = 0ull, cst1 = 0ull, cst2 = 0ull, cst3 = 0ull, cst4 = 0ull;

    __syncthreads();

    #pragma unroll 1
    for (int t = 0; t < SEQLEN; t++) {
        const u64* __restrict__ hb = &hsh[t & 1][0][0];
        u64* __restrict__ hw = &hsh[(t + 1) & 1][0][0];
        const float* __restrict__ xrow = &xsh[t][0];

        // ---- deferred FC for step t-1 (idle lanes; stable buffer) ----
        if (fcRole && t > 0) {
            const u64* __restrict__ hv = hb + fb * KP;
            u64 s0 = 0ull, s1 = 0ull;
            #pragma unroll
            for (int q = 0; q < KP; q += 2) {
                s0 = ffma2(hv[q],     wfc2[q],     s0);
                s1 = ffma2(hv[q + 1], wfc2[q + 1], s1);
            }
            float aa, ab, ac, ad;
            upk2(s0, aa, ab); upk2(s1, ac, ad);
            if (b0 + fb < BATCH)
                out[(b0 + fb) * SEQLEN + (t - 1)] = (aa + ab) + (ac + ad) + bfc;
        }

        if (active) {
            // dot products for a pair of batches (cb, cb+1)
            auto dots2 = [&](int cb, u64& A0, u64& A1, u64& C0, u64& C1) {
                A0 = 0ull; A1 = 0ull; C0 = 0ull; C1 = 0ull;
                #pragma unroll
                for (int q = 0; q < KP; q += 2) {
                    ulonglong2 u0 = *(const ulonglong2*)(hb + cb * KP + q);
                    ulonglong2 u1 = *(const ulonglong2*)(hb + (cb + 1) * KP + q);
                    A0 = ffma2(w1[q], u0.x, A0); A0 = ffma2(w1[q + 1], u0.y, A0);
                    A1 = ffma2(w1[q], u1.x, A1); A1 = ffma2(w1[q + 1], u1.y, A1);
                    C0 = ffma2(w2[q], u0.x, C0); C0 = ffma2(w2[q + 1], u0.y, C0);
                    C1 = ffma2(w2[q], u1.x, C1); C1 = ffma2(w2[q + 1], u1.y, C1);
                }
            };
            // tail for a pair of batches: acts, exchange, cell/h update
            auto tail2 = [&](int cb, u64 A0, u64 A1, u64 C0, u64 C1, u64& cc) {
                const float2 xv = make_float2(xrow[cb], xrow[cb + 1]);
                float lo, hi;
                upk2(A0, lo, hi); const float g10 = (lo + hi) + fmaf(xv.x, wih1, bias1);
                upk2(A1, lo, hi); const float g11 = (lo + hi) + fmaf(xv.y, wih1, bias1);
                upk2(C0, lo, hi); const float g20 = (lo + hi) + fmaf(xv.x, wih2, bias2);
                upk2(C1, lo, hi); const float g21 = (lo + hi) + fmaf(xv.y, wih2, bias2);
                const float s10 = fmaf(0.5f, tanha(0.5f * g10), 0.5f);
                const float s11 = fmaf(0.5f, tanha(0.5f * g11), 0.5f);
                const float s20 = fmaf(m2, tanha(sc2 * g20), a2c);
                const float s21 = fmaf(m2, tanha(sc2 * g21), a2c);
                u64 a1p = pk2(s10, s11);
                u64 a2p = pk2(s20, s21);
                u64 pr  = fmul2(a1p, a2p);             // p0: sig(i)*tanh(g)
                u64 rr  = __shfl_xor_sync(wmask, pr, 1, 32);
                if (p == 1) {
                    cc = ffma2(a1p, cc, rr);           // c = sig(f)*c + i*g
                    float c0f, c1f; upk2(cc, c0f, c1f);
                    const float h0v = s20 * tanha(c0f);
                    const float h1v = s21 * tanha(c1f);
                    const int jh = j >> 1, jl = j & 1;
                    ((float*)(hw + cb * KP + jh))[jl]       = h0v;
                    ((float*)(hw + (cb + 1) * KP + jh))[jl] = h1v;
                }
            };

            u64 A0a, A1a, C0a, C1a, A0b, A1b, C0b, C1b;

            // stage -1: dots(0,1)
            dots2(0, A0a, A1a, C0a, C1a);
            dots2(2, A0b, A1b, C0b, C1b);
            asm volatile("" ::: "memory");
            // stage 0: dots(2) overlapped with tails(0,1)
            u64 A0c, A1c, C0c, C1c;
            dots2(4, A0c, A1c, C0c, C1c);
            tail2(0, A0a, A1a, C0a, C1a, cst0);
            tail2(2, A0b, A1b, C0b, C1b, cst1);
            asm volatile("" ::: "memory");
            // stage 1: dots(3,4) overlapped with tail(2)
            dots2(6, A0a, A1a, C0a, C1a);
            dots2(8, A0b, A1b, C0b, C1b);
            tail2(4, A0c, A1c, C0c, C1c, cst2);
            asm volatile("" ::: "memory");
            // stage 2: tails(3,4)
            tail2(6, A0a, A1a, C0a, C1a, cst3);
            tail2(8, A0b, A1b, C0b, C1b, cst4);
        }
        __syncthreads();
    }

    // final FC for t = SEQLEN-1
    if (fcRole && b0 + fb < BATCH) {
        const u64* __restrict__ hv = &hsh[SEQLEN & 1][fb][0];
        u64 s0 = 0ull, s1 = 0ull;
        #pragma unroll
        for (int q = 0; q < KP; q += 2) {
            s0 = ffma2(hv[q],     wfc2[q],     s0);
            s1 = ffma2(hv[q + 1], wfc2[q + 1], s1);
        }
        float aa, ab, ac, ad;
        upk2(s0, aa, ab); upk2(s1, ac, ad);
        out[(b0 + fb) * SEQLEN + (SEQLEN - 1)] = (aa + ab) + (ac + ad) + bfc;
    }
}

extern "C" void kernel_launch(void* const* d_in, const int* in_sizes, int n_in,
                              void* d_out, int out_size) {
    const float* input = (const float*)d_in[0];
    const float* W_ih  = (const float*)d_in[1];
    const float* W_hh  = (const float*)d_in[2];
    const float* b_ih  = (const float*)d_in[3];
    const float* b_hh  = (const float*)d_in[4];
    const float* W_fc  = (const float*)d_in[5];
    const float* b_fc  = (const float*)d_in[6];
    // d_in[7] = future (0) — ignored.
    float* out = (float*)d_out;

    lstm12_kernel<<<GRID, NTHR>>>(input, W_ih, W_hh, b_ih, b_hh,
                                  W_fc, b_fc, out);
}